// round 1
// baseline (speedup 1.0000x reference)
#include <cuda_runtime.h>
#include <math.h>

#define N 1024
#define DIM 64
#define EMB_H 64
#define HID 256   // DIM*EXP
#define K 16

__device__ float g_q[N * DIM];
__device__ float g_k[N * DIM];
__device__ float g_v[N * DIM];
__device__ int   g_nbr[N * K];

// ---------------------------------------------------------------------------
// Kernel 1: q,k,v = x @ Wq/Wk/Wv   (one block per row, 64 threads)
// ---------------------------------------------------------------------------
__global__ void qkv_kernel(const float* __restrict__ x,
                           const float* __restrict__ Wq,
                           const float* __restrict__ Wk,
                           const float* __restrict__ Wv) {
    int n = blockIdx.x;
    int d = threadIdx.x;  // 0..63
    __shared__ float xs[DIM];
    xs[d] = x[n * DIM + d];
    __syncthreads();
    float q = 0.f, k = 0.f, v = 0.f;
#pragma unroll 8
    for (int c = 0; c < DIM; c++) {
        float xv = xs[c];
        q += xv * Wq[c * DIM + d];
        k += xv * Wk[c * DIM + d];
        v += xv * Wv[c * DIM + d];
    }
    g_q[n * DIM + d] = q;
    g_k[n * DIM + d] = k;
    g_v[n * DIM + d] = v;
}

// ---------------------------------------------------------------------------
// Kernel 2: kNN (squared euclidean, smallest K, ties -> lowest index)
// one block per query point, 256 threads
// ---------------------------------------------------------------------------
__global__ void knn_kernel(const float* __restrict__ pos) {
    int i = blockIdx.x;
    int tid = threadIdx.x;  // 0..255
    __shared__ float d2[N];
    __shared__ float wval[8];
    __shared__ int   widx[8];
    __shared__ float selv;
    __shared__ int   seli;

    float px = pos[i * 3 + 0], py = pos[i * 3 + 1], pz = pos[i * 3 + 2];
    for (int j = tid; j < N; j += 256) {
        float dx = px - pos[j * 3 + 0];
        float dy = py - pos[j * 3 + 1];
        float dz = pz - pos[j * 3 + 2];
        d2[j] = dx * dx + dy * dy + dz * dz;
    }
    __syncthreads();

    for (int r = 0; r < K; r++) {
        float bv = 3.4e38f;
        int   bi = N;
        for (int j = tid; j < N; j += 256) {
            float v = d2[j];
            if (v < bv || (v == bv && j < bi)) { bv = v; bi = j; }
        }
        // warp reduce (min, tie -> lowest index)
#pragma unroll
        for (int off = 16; off > 0; off >>= 1) {
            float ov = __shfl_down_sync(0xffffffffu, bv, off);
            int   oi = __shfl_down_sync(0xffffffffu, bi, off);
            if (ov < bv || (ov == bv && oi < bi)) { bv = ov; bi = oi; }
        }
        if ((tid & 31) == 0) { wval[tid >> 5] = bv; widx[tid >> 5] = bi; }
        __syncthreads();
        if (tid == 0) {
#pragma unroll
            for (int w = 1; w < 8; w++) {
                if (wval[w] < bv || (wval[w] == bv && widx[w] < bi)) {
                    bv = wval[w]; bi = widx[w];
                }
            }
            g_nbr[i * K + r] = bi;
            d2[bi] = 3.4e38f;   // remove from further consideration
        }
        __syncthreads();
    }
}

// ---------------------------------------------------------------------------
// Kernel 3: per-pair MLPs + softmax aggregation
// one block per query point, 512 threads
// ---------------------------------------------------------------------------
__global__ __launch_bounds__(512)
void main_kernel(const float* __restrict__ pos,
                 const float* __restrict__ P1, const float* __restrict__ pb1,
                 const float* __restrict__ P2, const float* __restrict__ pb2,
                 const float* __restrict__ A1, const float* __restrict__ ab1,
                 const float* __restrict__ A2, const float* __restrict__ ab2,
                 float* __restrict__ out) {
    int i = blockIdx.x;
    int tid = threadIdx.x;

    __shared__ float qrow[DIM];
    __shared__ int   nb[K];
    __shared__ float rp[K][4];          // rel_pos (3 used)
    __shared__ float E[K][EMB_H];       // relu(rel_pos @ P1 + pb1)
    __shared__ float T[K][DIM];         // qk_g + rpe_g
    __shared__ float VG[K][DIM];        // v_g + rpe_g
    __shared__ float H[K][HID];         // relu(T @ A1 + ab1)
    __shared__ float SIM[K][DIM];

    if (tid < DIM) qrow[tid] = g_q[i * DIM + tid];
    if (tid < K)   nb[tid] = g_nbr[i * K + tid];
    __syncthreads();
    if (tid < K * 3) {
        int kk = tid / 3, c = tid % 3;
        rp[kk][c] = pos[i * 3 + c] - pos[nb[kk] * 3 + c];
    }
    __syncthreads();

    // Phase 1a: E[kk][h] = relu(rp . P1[:,h] + pb1[h])   (1024 outputs)
    for (int t = tid; t < K * EMB_H; t += 512) {
        int kk = t >> 6, h = t & 63;
        float e = rp[kk][0] * P1[h] + rp[kk][1] * P1[EMB_H + h]
                + rp[kk][2] * P1[2 * EMB_H + h] + pb1[h];
        E[kk][h] = fmaxf(e, 0.f);
    }
    __syncthreads();

    // Phase 1b: rpe = E @ P2 + pb2 ; T = q - k + rpe ; VG = v + rpe
    for (int t = tid; t < K * DIM; t += 512) {
        int kk = t >> 6, d = t & 63;
        float acc = pb2[d];
        const float* Ek = E[kk];
#pragma unroll 8
        for (int h = 0; h < EMB_H; h++) acc += Ek[h] * P2[h * DIM + d];
        int j = nb[kk];
        T[kk][d]  = qrow[d] - g_k[j * DIM + d] + acc;
        VG[kk][d] = g_v[j * DIM + d] + acc;
    }
    __syncthreads();

    // Phase 2: H[kk][e] = relu(sum_d T[kk][d]*A1[d][e] + ab1[e])
    {
        int e = tid & 255;
        int g = tid >> 8;  // 0..1 -> kk base g*8
        float acc[8];
#pragma unroll
        for (int u = 0; u < 8; u++) acc[u] = ab1[e];
#pragma unroll 4
        for (int d = 0; d < DIM; d++) {
            float a1 = A1[d * HID + e];
#pragma unroll
            for (int u = 0; u < 8; u++) acc[u] += T[g * 8 + u][d] * a1;
        }
#pragma unroll
        for (int u = 0; u < 8; u++) H[g * 8 + u][e] = fmaxf(acc[u], 0.f);
    }
    __syncthreads();

    // Phase 3: SIM[kk][d] = sum_e H[kk][e]*A2[e][d] + ab2[d]
    {
        int d = tid & 63;
        int g = tid >> 6;  // 0..7 -> handles kk=g and kk=g+8
        float acc0 = ab2[d], acc1 = ab2[d];
#pragma unroll 4
        for (int e = 0; e < HID; e++) {
            float a2 = A2[e * DIM + d];
            acc0 += H[g][e] * a2;
            acc1 += H[g + 8][e] * a2;
        }
        SIM[g][d] = acc0;
        SIM[g + 8][d] = acc1;
    }
    __syncthreads();

    // Phase 4: softmax over neighbors (per-dim) + weighted sum of VG
    if (tid < DIM) {
        int d = tid;
        float m = -3.4e38f;
#pragma unroll
        for (int kk = 0; kk < K; kk++) m = fmaxf(m, SIM[kk][d]);
        float s = 0.f, agg = 0.f;
#pragma unroll
        for (int kk = 0; kk < K; kk++) {
            float w = expf(SIM[kk][d] - m);
            s += w;
            agg += w * VG[kk][d];
        }
        out[i * DIM + d] = agg / s;
    }
}

// ---------------------------------------------------------------------------
// launch
// ---------------------------------------------------------------------------
extern "C" void kernel_launch(void* const* d_in, const int* in_sizes, int n_in,
                              void* d_out, int out_size) {
    const float* x   = (const float*)d_in[0];
    const float* pos = (const float*)d_in[1];
    const float* Wq  = (const float*)d_in[2];
    const float* Wk  = (const float*)d_in[3];
    const float* Wv  = (const float*)d_in[4];
    const float* P1  = (const float*)d_in[5];
    const float* pb1 = (const float*)d_in[6];
    const float* P2  = (const float*)d_in[7];
    const float* pb2 = (const float*)d_in[8];
    const float* A1  = (const float*)d_in[9];
    const float* ab1 = (const float*)d_in[10];
    const float* A2  = (const float*)d_in[11];
    const float* ab2 = (const float*)d_in[12];
    float* out = (float*)d_out;

    qkv_kernel<<<N, DIM>>>(x, Wq, Wk, Wv);
    knn_kernel<<<N, 256>>>(pos);
    main_kernel<<<N, 512>>>(pos, P1, pb1, P2, pb2, A1, ab1, A2, ab2, out);
}

// round 2
// speedup vs baseline: 2.3713x; 2.3713x over previous
#include <cuda_runtime.h>
#include <math.h>

#define NPTS 1024
#define DIM  64
#define HID  256
#define K    16
#define QB   8            // queries per main-kernel block
#define RB   (QB * K)     // 128 pair rows per block

typedef unsigned long long ull;

__device__ float g_q[NPTS * DIM];
__device__ float g_k[NPTS * DIM];
__device__ float g_v[NPTS * DIM];
__device__ int   g_nbr[NPTS * K];

// ---------------- packed fp32x2 helpers (Blackwell FFMA2 path) ----------------
__device__ __forceinline__ ull fma2(ull a, ull b, ull c) {
    ull d; asm("fma.rn.f32x2 %0, %1, %2, %3;" : "=l"(d) : "l"(a), "l"(b), "l"(c));
    return d;
}
__device__ __forceinline__ ull dup2(float x) {
    ull d; asm("mov.b64 %0, {%1, %1};" : "=l"(d) : "f"(x)); return d;
}
__device__ __forceinline__ ull pack2(float x, float y) {
    ull d; asm("mov.b64 %0, {%1, %2};" : "=l"(d) : "f"(x), "f"(y)); return d;
}
__device__ __forceinline__ float2 up2(ull v) {
    float2 r; asm("mov.b64 {%0, %1}, %2;" : "=f"(r.x), "=f"(r.y) : "l"(v)); return r;
}

// ---------------------------------------------------------------------------
// Kernel 1: q,k,v = x @ Wq/Wk/Wv.  grid 128, block 256, 8 rows per block.
// ---------------------------------------------------------------------------
__global__ __launch_bounds__(256)
void qkv_kernel(const float* __restrict__ x,
                const float* __restrict__ Wq,
                const float* __restrict__ Wk,
                const float* __restrict__ Wv) {
    __shared__ float xs[8 * DIM];
    int tid = threadIdx.x;
    int rb = blockIdx.x * 8;
    for (int t = tid; t < 8 * DIM; t += 256) xs[t] = x[rb * DIM + t];
    __syncthreads();

    int d = tid & 63;
    int rg = tid >> 6;           // 0..3 ; rows rg and rg+4
    float qa = 0.f, qb = 0.f, ka = 0.f, kb = 0.f, va = 0.f, vb = 0.f;
#pragma unroll 4
    for (int c = 0; c < DIM; c++) {
        float wq = Wq[c * DIM + d], wk = Wk[c * DIM + d], wv = Wv[c * DIM + d];
        float xa = xs[rg * DIM + c], xb = xs[(rg + 4) * DIM + c];
        qa += xa * wq; qb += xb * wq;
        ka += xa * wk; kb += xb * wk;
        va += xa * wv; vb += xb * wv;
    }
    g_q[(rb + rg) * DIM + d] = qa;  g_q[(rb + rg + 4) * DIM + d] = qb;
    g_k[(rb + rg) * DIM + d] = ka;  g_k[(rb + rg + 4) * DIM + d] = kb;
    g_v[(rb + rg) * DIM + d] = va;  g_v[(rb + rg + 4) * DIM + d] = vb;
}

// ---------------------------------------------------------------------------
// Kernel 2: kNN, warp-synchronous selection. grid 1024, block 256.
// ---------------------------------------------------------------------------
__global__ __launch_bounds__(256)
void knn_kernel(const float* __restrict__ pos) {
    __shared__ float ps[NPTS * 3];
    __shared__ float cval[128];
    __shared__ int   cidx[128];

    int i = blockIdx.x;
    int tid = threadIdx.x;
    for (int t = tid; t < NPTS * 3; t += 256) ps[t] = pos[t];
    __syncthreads();

    float px = ps[i * 3 + 0], py = ps[i * 3 + 1], pz = ps[i * 3 + 2];
    int w = tid >> 5, lane = tid & 31;

    float v[4]; int id[4];
#pragma unroll
    for (int c = 0; c < 4; c++) {
        int j = w * 128 + c * 32 + lane;
        float dx = px - ps[j * 3 + 0];
        float dy = py - ps[j * 3 + 1];
        float dz = pz - ps[j * 3 + 2];
        v[c] = dx * dx + dy * dy + dz * dz;
        id[c] = j;
    }
    // per-warp top-16 (no block barriers)
    for (int r = 0; r < K; r++) {
        float bv = v[0]; int bi = id[0];
#pragma unroll
        for (int c = 1; c < 4; c++)
            if (v[c] < bv || (v[c] == bv && id[c] < bi)) { bv = v[c]; bi = id[c]; }
#pragma unroll
        for (int off = 16; off > 0; off >>= 1) {
            float ov = __shfl_down_sync(0xffffffffu, bv, off);
            int   oi = __shfl_down_sync(0xffffffffu, bi, off);
            if (ov < bv || (ov == bv && oi < bi)) { bv = ov; bi = oi; }
        }
        bv = __shfl_sync(0xffffffffu, bv, 0);
        bi = __shfl_sync(0xffffffffu, bi, 0);
        if (lane == 0) { cval[w * 16 + r] = bv; cidx[w * 16 + r] = bi; }
#pragma unroll
        for (int c = 0; c < 4; c++) if (id[c] == bi) v[c] = 3.4e38f;
    }
    __syncthreads();

    // warp 0 merges 128 candidates
    if (w == 0) {
        float mv[4]; int mi[4];
#pragma unroll
        for (int c = 0; c < 4; c++) { mv[c] = cval[c * 32 + lane]; mi[c] = cidx[c * 32 + lane]; }
        for (int r = 0; r < K; r++) {
            float bv = mv[0]; int bi = mi[0];
#pragma unroll
            for (int c = 1; c < 4; c++)
                if (mv[c] < bv || (mv[c] == bv && mi[c] < bi)) { bv = mv[c]; bi = mi[c]; }
#pragma unroll
            for (int off = 16; off > 0; off >>= 1) {
                float ov = __shfl_down_sync(0xffffffffu, bv, off);
                int   oi = __shfl_down_sync(0xffffffffu, bi, off);
                if (ov < bv || (ov == bv && oi < bi)) { bv = ov; bi = oi; }
            }
            bi = __shfl_sync(0xffffffffu, bi, 0);
            if (lane == 0) g_nbr[i * K + r] = bi;
#pragma unroll
            for (int c = 0; c < 4; c++) if (mi[c] == bi) mv[c] = 3.4e38f;
        }
    }
}

// ---------------------------------------------------------------------------
// Kernel 3: per-pair MLPs + softmax aggregation. grid 128, block 512.
// Dynamic smem layout (floats):
//   [0      , 8192 )  T   (later aliased as SIM)
//   [8192   , 16384)  VG
//   [16384  , 32768)  Hh (half of H, 128x128) ; E aliases [16384,24576)
//                     P2i aliases [24576,28672)
//   [32768  , 49152)  A2i (interleaved e-pairs)
// ---------------------------------------------------------------------------
#define SMEM_FLOATS 49152

__global__ __launch_bounds__(512)
void main_kernel(const float* __restrict__ pos,
                 const float* __restrict__ P1, const float* __restrict__ pb1,
                 const float* __restrict__ P2, const float* __restrict__ pb2,
                 const float* __restrict__ A1, const float* __restrict__ ab1,
                 const float* __restrict__ A2, const float* __restrict__ ab2,
                 float* __restrict__ out) {
    extern __shared__ float sm[];
    float* T   = sm;                 // 128 x 64
    float* VG  = sm + 8192;          // 128 x 64
    float* Hh  = sm + 16384;         // 128 x 128
    float* E   = Hh;                 // 128 x 64 (phase 1 only)
    float* P2i = Hh + 8192;          // 4096 (phase 1 only)
    float* A2i = sm + 32768;         // 16384

    __shared__ int   nb[RB];
    __shared__ float rp[RB][3];
    __shared__ float qrow[QB * DIM];

    int tid = threadIdx.x;
    int ib = blockIdx.x * QB;

    // ---- Phase 0: stage ----
    for (int t = tid; t < RB; t += 512) nb[t] = g_nbr[ib * K + t];
    for (int t = tid; t < QB * DIM; t += 512) qrow[t] = g_q[ib * DIM + t];
    for (int t = tid; t < 16384; t += 512) {
        int s = t & 1, d = (t >> 1) & 63, e2 = t >> 7;
        A2i[t] = A2[(2 * e2 + s) * DIM + d];
    }
    for (int t = tid; t < 4096; t += 512) {
        int s = t & 1, d = (t >> 1) & 63, h2 = t >> 7;
        P2i[t] = P2[(2 * h2 + s) * DIM + d];
    }
    __syncthreads();
    for (int t = tid; t < RB * 3; t += 512) {
        int r = t / 3, c = t - r * 3;
        int i = ib + (r >> 4);
        rp[r][c] = pos[i * 3 + c] - pos[nb[r] * 3 + c];
    }
    __syncthreads();

    // ---- Phase 1a: E = relu(rp @ P1 + pb1) ----
    for (int t = tid; t < RB * 64; t += 512) {
        int r = t >> 6, h = t & 63;
        float e = rp[r][0] * P1[h] + rp[r][1] * P1[64 + h]
                + rp[r][2] * P1[128 + h] + pb1[h];
        E[t] = fmaxf(e, 0.f);
    }
    __syncthreads();

    int w = tid >> 5, lane = tid & 31;
    int r0 = w * 8;
    int d0 = lane, d1 = lane + 32;

    // ---- Phase 1b: rpe = E @ P2 + pb2 ; T = q - k + rpe ; VG = v + rpe ----
    {
        ull aA[8], aB[8];
#pragma unroll
        for (int u = 0; u < 8; u++) { aA[u] = 0ULL; aB[u] = 0ULL; }
#pragma unroll 4
        for (int h2 = 0; h2 < 32; h2++) {
            ull p0 = *(const ull*)(P2i + (((h2 << 6) + d0) << 1));
            ull p1 = *(const ull*)(P2i + (((h2 << 6) + d1) << 1));
#pragma unroll
            for (int u = 0; u < 8; u++) {
                ull ev = *(const ull*)(E + ((r0 + u) << 6) + (h2 << 1));
                aA[u] = fma2(ev, p0, aA[u]);
                aB[u] = fma2(ev, p1, aB[u]);
            }
        }
        float b0 = pb2[d0], b1 = pb2[d1];
#pragma unroll
        for (int u = 0; u < 8; u++) {
            int r = r0 + u;
            int j = nb[r];
            int qq = r >> 4;
            float2 fa = up2(aA[u]); float rpe0 = fa.x + fa.y + b0;
            float2 fb = up2(aB[u]); float rpe1 = fb.x + fb.y + b1;
            T[r * 64 + d0]  = qrow[qq * 64 + d0] - g_k[j * 64 + d0] + rpe0;
            VG[r * 64 + d0] = g_v[j * 64 + d0] + rpe0;
            T[r * 64 + d1]  = qrow[qq * 64 + d1] - g_k[j * 64 + d1] + rpe1;
            VG[r * 64 + d1] = g_v[j * 64 + d1] + rpe1;
        }
    }
    __syncthreads();

    // ---- Phases 2+3 over two e-halves; phase-3 accumulators persist ----
    ull sA[8], sB[8];
#pragma unroll
    for (int u = 0; u < 8; u++) { sA[u] = 0ULL; sB[u] = 0ULL; }
    int e0 = lane << 2;

    for (int half = 0; half < 2; half++) {
        // Phase 2: Hh = relu(T @ A1[:, half*128 : half*128+128] + ab1)
        {
            const float* A1h = A1 + half * 128 + e0;
            float4 b = *(const float4*)(ab1 + half * 128 + e0);
            ull acc0[8], acc1[8];
#pragma unroll
            for (int u = 0; u < 8; u++) {
                acc0[u] = pack2(b.x, b.y);
                acc1[u] = pack2(b.z, b.w);
            }
#pragma unroll 4
            for (int d = 0; d < DIM; d++) {
                ulonglong2 av = *(const ulonglong2*)(A1h + d * HID);
#pragma unroll
                for (int u = 0; u < 8; u++) {
                    ull tt = dup2(T[((r0 + u) << 6) + d]);
                    acc0[u] = fma2(tt, av.x, acc0[u]);
                    acc1[u] = fma2(tt, av.y, acc1[u]);
                }
            }
#pragma unroll
            for (int u = 0; u < 8; u++) {
                float2 h0 = up2(acc0[u]);
                float2 h1 = up2(acc1[u]);
                float4 hv = make_float4(fmaxf(h0.x, 0.f), fmaxf(h0.y, 0.f),
                                        fmaxf(h1.x, 0.f), fmaxf(h1.y, 0.f));
                *(float4*)(Hh + ((r0 + u) << 7) + e0) = hv;
            }
        }
        __syncthreads();

        // Phase 3 accumulate: SIM += Hh @ A2[half*128 : half*128+128, :]
#pragma unroll 4
        for (int e2l = 0; e2l < 64; e2l++) {
            int e2 = (half << 6) + e2l;
            ull a0 = *(const ull*)(A2i + (((e2 << 6) + d0) << 1));
            ull a1 = *(const ull*)(A2i + (((e2 << 6) + d1) << 1));
#pragma unroll
            for (int u = 0; u < 8; u++) {
                ull hv = *(const ull*)(Hh + ((r0 + u) << 7) + (e2l << 1));
                sA[u] = fma2(hv, a0, sA[u]);
                sB[u] = fma2(hv, a1, sB[u]);
            }
        }
        __syncthreads();
    }

    // ---- Phase 3 epilogue: SIM (aliases T) ----
    {
        float b0 = ab2[d0], b1 = ab2[d1];
#pragma unroll
        for (int u = 0; u < 8; u++) {
            int r = r0 + u;
            float2 fa = up2(sA[u]);
            float2 fb = up2(sB[u]);
            T[r * 64 + d0] = fa.x + fa.y + b0;
            T[r * 64 + d1] = fb.x + fb.y + b1;
        }
    }
    __syncthreads();

    // ---- Phase 4: softmax over K neighbors, weighted sum of VG ----
    {
        int qq = tid >> 6, d = tid & 63;
        int base = qq * K;
        float m = -3.4e38f;
#pragma unroll
        for (int kk = 0; kk < K; kk++) m = fmaxf(m, T[(base + kk) * 64 + d]);
        float s = 0.f, agg = 0.f;
#pragma unroll
        for (int kk = 0; kk < K; kk++) {
            float wv = __expf(T[(base + kk) * 64 + d] - m);
            s += wv;
            agg += wv * VG[(base + kk) * 64 + d];
        }
        out[(ib + qq) * 64 + d] = agg / s;
    }
}

// ---------------------------------------------------------------------------
extern "C" void kernel_launch(void* const* d_in, const int* in_sizes, int n_in,
                              void* d_out, int out_size) {
    const float* x   = (const float*)d_in[0];
    const float* pos = (const float*)d_in[1];
    const float* Wq  = (const float*)d_in[2];
    const float* Wk  = (const float*)d_in[3];
    const float* Wv  = (const float*)d_in[4];
    const float* P1  = (const float*)d_in[5];
    const float* pb1 = (const float*)d_in[6];
    const float* P2  = (const float*)d_in[7];
    const float* pb2 = (const float*)d_in[8];
    const float* A1  = (const float*)d_in[9];
    const float* ab1 = (const float*)d_in[10];
    const float* A2  = (const float*)d_in[11];
    const float* ab2 = (const float*)d_in[12];
    float* out = (float*)d_out;

    cudaFuncSetAttribute(main_kernel, cudaFuncAttributeMaxDynamicSharedMemorySize,
                         SMEM_FLOATS * sizeof(float));

    qkv_kernel<<<128, 256>>>(x, Wq, Wk, Wv);
    knn_kernel<<<NPTS, 256>>>(pos);
    main_kernel<<<128, 512, SMEM_FLOATS * sizeof(float)>>>(
        pos, P1, pb1, P2, pb2, A1, ab1, A2, ab2, out);
}

// round 3
// speedup vs baseline: 2.7983x; 1.1801x over previous
#include <cuda_runtime.h>
#include <math.h>

#define NPTS 1024
#define DIM  64
#define HID  256
#define K    16
#define QB   8            // queries per block
#define RB   (QB * K)     // 128 pair rows per block
#define GRID 128
#define NT   512

typedef unsigned long long ull;

__device__ float g_k[NPTS * DIM];
__device__ float g_v[NPTS * DIM];
__device__ unsigned g_bar;   // zero-initialized; advances by GRID per launch

// ---------------- packed fp32x2 helpers ----------------
__device__ __forceinline__ ull fma2(ull a, ull b, ull c) {
    ull d; asm("fma.rn.f32x2 %0, %1, %2, %3;" : "=l"(d) : "l"(a), "l"(b), "l"(c));
    return d;
}
__device__ __forceinline__ ull dup2(float x) {
    ull d; asm("mov.b64 %0, {%1, %1};" : "=l"(d) : "f"(x)); return d;
}
__device__ __forceinline__ ull pack2(float x, float y) {
    ull d; asm("mov.b64 %0, {%1, %2};" : "=l"(d) : "f"(x), "f"(y)); return d;
}
__device__ __forceinline__ float2 up2(ull v) {
    float2 r; asm("mov.b64 {%0, %1}, %2;" : "=f"(r.x), "=f"(r.y) : "l"(v)); return r;
}

// ---------------------------------------------------------------------------
// Fused kernel. grid 128, block 512, 192KB dynamic smem.
// Dynamic smem (floats):
//   [0      , 8192 )  T (later aliased as SIM)
//   [8192   , 16384)  VG
//   [16384  , 32768)  Hh (128x128); E aliases [16384,24576); P2i aliases [24576,28672)
//   [32768  , 49152)  A2i ; ps (pos staging, 3072 floats) aliases [32768,35840) early
// ---------------------------------------------------------------------------
#define SMEM_FLOATS 49152

__global__ __launch_bounds__(NT)
void fused_kernel(const float* __restrict__ x,
                  const float* __restrict__ pos,
                  const float* __restrict__ Wq,
                  const float* __restrict__ Wk,
                  const float* __restrict__ Wv,
                  const float* __restrict__ P1, const float* __restrict__ pb1,
                  const float* __restrict__ P2, const float* __restrict__ pb2,
                  const float* __restrict__ A1, const float* __restrict__ ab1,
                  const float* __restrict__ A2, const float* __restrict__ ab2,
                  float* __restrict__ out) {
    extern __shared__ float sm[];
    float* T   = sm;
    float* VG  = sm + 8192;
    float* Hh  = sm + 16384;
    float* E   = Hh;
    float* P2i = Hh + 8192;
    float* A2i = sm + 32768;
    float* ps  = sm + 32768;         // aliases A2i during prolog

    __shared__ int   nb[RB];
    __shared__ float rp[RB][3];
    __shared__ float qrow[QB * DIM];
    __shared__ float xs[QB * DIM];
    __shared__ float cval[QB][2][K];
    __shared__ int   cidx[QB][2][K];
    __shared__ unsigned s_ticket;

    int tid = threadIdx.x;
    int ib = blockIdx.x * QB;
    int w = tid >> 5, lane = tid & 31;

    // ---- Step 0: stage pos, x rows, P2 interleaved ----
    for (int t = tid; t < NPTS * 3; t += NT) ps[t] = pos[t];
    for (int t = tid; t < QB * DIM; t += NT) xs[t] = x[ib * DIM + t];
    for (int t = tid; t < 4096; t += NT) {
        int s = t & 1, d = (t >> 1) & 63, h2 = t >> 7;
        P2i[t] = P2[(2 * h2 + s) * DIM + d];
    }
    __syncthreads();

    // ---- Step 1: qkv for this block's 8 rows ----
    {
        int r = tid >> 6, d = tid & 63;
        float q = 0.f, kk = 0.f, vv = 0.f;
#pragma unroll 4
        for (int c = 0; c < DIM; c++) {
            float xv = xs[r * DIM + c];
            q  += xv * Wq[c * DIM + d];
            kk += xv * Wk[c * DIM + d];
            vv += xv * Wv[c * DIM + d];
        }
        qrow[r * DIM + d] = q;
        g_k[(ib + r) * DIM + d] = kk;
        g_v[(ib + r) * DIM + d] = vv;
    }
    __syncthreads();
    if (tid == 0) {
        __threadfence();
        s_ticket = atomicAdd(&g_bar, 1u);
    }

    // ---- Step 2: kNN for 8 queries (2 warps per query, 512 candidates each) ----
    {
        int qq = w >> 1, hh = w & 1;
        int gi = ib + qq;
        float px = ps[gi * 3 + 0], py = ps[gi * 3 + 1], pz = ps[gi * 3 + 2];
        float v[16]; int id[16];
#pragma unroll
        for (int c = 0; c < 16; c++) {
            int j = hh * 512 + c * 32 + lane;
            float dx = px - ps[j * 3 + 0];
            float dy = py - ps[j * 3 + 1];
            float dz = pz - ps[j * 3 + 2];
            v[c] = dx * dx + dy * dy + dz * dz;
            id[c] = j;
        }
        for (int r = 0; r < K; r++) {
            float bv = v[0]; int bi = id[0];
#pragma unroll
            for (int c = 1; c < 16; c++)
                if (v[c] < bv || (v[c] == bv && id[c] < bi)) { bv = v[c]; bi = id[c]; }
#pragma unroll
            for (int off = 16; off > 0; off >>= 1) {
                float ov = __shfl_down_sync(0xffffffffu, bv, off);
                int   oi = __shfl_down_sync(0xffffffffu, bi, off);
                if (ov < bv || (ov == bv && oi < bi)) { bv = ov; bi = oi; }
            }
            bv = __shfl_sync(0xffffffffu, bv, 0);
            bi = __shfl_sync(0xffffffffu, bi, 0);
            if (lane == 0) { cval[qq][hh][r] = bv; cidx[qq][hh][r] = bi; }
#pragma unroll
            for (int c = 0; c < 16; c++) if (id[c] == bi) v[c] = 3.4e38f;
        }
    }
    __syncthreads();
    // merge the two halves per query: even warps, 32 candidates on 32 lanes
    if ((w & 1) == 0) {
        int qq = w >> 1;
        float mv = cval[qq][lane >> 4][lane & 15];
        int   mi = cidx[qq][lane >> 4][lane & 15];
        for (int r = 0; r < K; r++) {
            float bv = mv; int bi = mi;
#pragma unroll
            for (int off = 16; off > 0; off >>= 1) {
                float ov = __shfl_down_sync(0xffffffffu, bv, off);
                int   oi = __shfl_down_sync(0xffffffffu, bi, off);
                if (ov < bv || (ov == bv && oi < bi)) { bv = ov; bi = oi; }
            }
            bi = __shfl_sync(0xffffffffu, bi, 0);
            if (lane == 0) nb[qq * K + r] = bi;
            if (mi == bi) mv = 3.4e38f;
        }
    }
    __syncthreads();

    // rel_pos from staged ps (before A2i overwrites it)
    for (int t = tid; t < RB * 3; t += NT) {
        int r = t / 3, c = t - r * 3;
        int gi = ib + (r >> 4);
        rp[r][c] = ps[gi * 3 + c] - ps[nb[r] * 3 + c];
    }
    __syncthreads();

    // ---- Step 3: stage A2 interleaved (overwrites ps); tid0 waits on barrier ----
    for (int t = tid; t < 16384; t += NT) {
        int s = t & 1, d = (t >> 1) & 63, e2 = t >> 7;
        A2i[t] = A2[(2 * e2 + s) * DIM + d];
    }
    if (tid == 0) {
        unsigned target = (s_ticket / GRID + 1u) * GRID;
        while ((int)(*(volatile unsigned*)&g_bar - target) < 0) { }
        __threadfence();
    }
    __syncthreads();

    // ---- Phase 1a: E = relu(rp @ P1 + pb1) ----
    for (int t = tid; t < RB * 64; t += NT) {
        int r = t >> 6, h = t & 63;
        float e = rp[r][0] * P1[h] + rp[r][1] * P1[64 + h]
                + rp[r][2] * P1[128 + h] + pb1[h];
        E[t] = fmaxf(e, 0.f);
    }
    __syncthreads();

    int r0 = w * 8;
    int d0 = lane, d1 = lane + 32;

    // ---- Phase 1b: rpe = E @ P2 + pb2 ; T = q - k + rpe ; VG = v + rpe ----
    {
        ull aA[8], aB[8];
#pragma unroll
        for (int u = 0; u < 8; u++) { aA[u] = 0ULL; aB[u] = 0ULL; }
#pragma unroll 4
        for (int h2 = 0; h2 < 32; h2++) {
            ull p0 = *(const ull*)(P2i + (((h2 << 6) + d0) << 1));
            ull p1 = *(const ull*)(P2i + (((h2 << 6) + d1) << 1));
#pragma unroll
            for (int u = 0; u < 8; u++) {
                ull ev = *(const ull*)(E + ((r0 + u) << 6) + (h2 << 1));
                aA[u] = fma2(ev, p0, aA[u]);
                aB[u] = fma2(ev, p1, aB[u]);
            }
        }
        float b0 = pb2[d0], b1 = pb2[d1];
#pragma unroll
        for (int u = 0; u < 8; u++) {
            int r = r0 + u;
            int j = nb[r];
            int qq = r >> 4;
            float2 fa = up2(aA[u]); float rpe0 = fa.x + fa.y + b0;
            float2 fb = up2(aB[u]); float rpe1 = fb.x + fb.y + b1;
            T[r * 64 + d0]  = qrow[qq * 64 + d0] - g_k[j * 64 + d0] + rpe0;
            VG[r * 64 + d0] = g_v[j * 64 + d0] + rpe0;
            T[r * 64 + d1]  = qrow[qq * 64 + d1] - g_k[j * 64 + d1] + rpe1;
            VG[r * 64 + d1] = g_v[j * 64 + d1] + rpe1;
        }
    }
    __syncthreads();

    // ---- Phases 2+3 over two e-halves; phase-3 accumulators persist ----
    ull sA[8], sB[8];
#pragma unroll
    for (int u = 0; u < 8; u++) { sA[u] = 0ULL; sB[u] = 0ULL; }
    int e0 = lane << 2;

    for (int half = 0; half < 2; half++) {
        {
            const float* A1h = A1 + half * 128 + e0;
            float4 b = *(const float4*)(ab1 + half * 128 + e0);
            ull acc0[8], acc1[8];
#pragma unroll
            for (int u = 0; u < 8; u++) {
                acc0[u] = pack2(b.x, b.y);
                acc1[u] = pack2(b.z, b.w);
            }
#pragma unroll 4
            for (int d = 0; d < DIM; d++) {
                ulonglong2 av = *(const ulonglong2*)(A1h + d * HID);
#pragma unroll
                for (int u = 0; u < 8; u++) {
                    ull tt = dup2(T[((r0 + u) << 6) + d]);
                    acc0[u] = fma2(tt, av.x, acc0[u]);
                    acc1[u] = fma2(tt, av.y, acc1[u]);
                }
            }
#pragma unroll
            for (int u = 0; u < 8; u++) {
                float2 h0 = up2(acc0[u]);
                float2 h1 = up2(acc1[u]);
                float4 hv = make_float4(fmaxf(h0.x, 0.f), fmaxf(h0.y, 0.f),
                                        fmaxf(h1.x, 0.f), fmaxf(h1.y, 0.f));
                *(float4*)(Hh + ((r0 + u) << 7) + e0) = hv;
            }
        }
        __syncthreads();

#pragma unroll 4
        for (int e2l = 0; e2l < 64; e2l++) {
            int e2 = (half << 6) + e2l;
            ull a0 = *(const ull*)(A2i + (((e2 << 6) + d0) << 1));
            ull a1 = *(const ull*)(A2i + (((e2 << 6) + d1) << 1));
#pragma unroll
            for (int u = 0; u < 8; u++) {
                ull hv = *(const ull*)(Hh + ((r0 + u) << 7) + (e2l << 1));
                sA[u] = fma2(hv, a0, sA[u]);
                sB[u] = fma2(hv, a1, sB[u]);
            }
        }
        __syncthreads();
    }

    // ---- Phase 3 epilogue: SIM (aliases T) ----
    {
        float b0 = ab2[d0], b1 = ab2[d1];
#pragma unroll
        for (int u = 0; u < 8; u++) {
            int r = r0 + u;
            float2 fa = up2(sA[u]);
            float2 fb = up2(sB[u]);
            T[r * 64 + d0] = fa.x + fa.y + b0;
            T[r * 64 + d1] = fb.x + fb.y + b1;
        }
    }
    __syncthreads();

    // ---- Phase 4: softmax over K neighbors + weighted sum of VG ----
    {
        int qq = tid >> 6, d = tid & 63;
        int base = qq * K;
        float m = -3.4e38f;
#pragma unroll
        for (int kk = 0; kk < K; kk++) m = fmaxf(m, T[(base + kk) * 64 + d]);
        float s = 0.f, agg = 0.f;
#pragma unroll
        for (int kk = 0; kk < K; kk++) {
            float wv = __expf(T[(base + kk) * 64 + d] - m);
            s += wv;
            agg += wv * VG[(base + kk) * 64 + d];
        }
        out[(ib + qq) * 64 + d] = agg / s;
    }
}

// ---------------------------------------------------------------------------
extern "C" void kernel_launch(void* const* d_in, const int* in_sizes, int n_in,
                              void* d_out, int out_size) {
    const float* x   = (const float*)d_in[0];
    const float* pos = (const float*)d_in[1];
    const float* Wq  = (const float*)d_in[2];
    const float* Wk  = (const float*)d_in[3];
    const float* Wv  = (const float*)d_in[4];
    const float* P1  = (const float*)d_in[5];
    const float* pb1 = (const float*)d_in[6];
    const float* P2  = (const float*)d_in[7];
    const float* pb2 = (const float*)d_in[8];
    const float* A1  = (const float*)d_in[9];
    const float* ab1 = (const float*)d_in[10];
    const float* A2  = (const float*)d_in[11];
    const float* ab2 = (const float*)d_in[12];
    float* out = (float*)d_out;

    cudaFuncSetAttribute(fused_kernel, cudaFuncAttributeMaxDynamicSharedMemorySize,
                         SMEM_FLOATS * sizeof(float));
    fused_kernel<<<GRID, NT, SMEM_FLOATS * sizeof(float)>>>(
        x, pos, Wq, Wk, Wv, P1, pb1, P2, pb2, A1, ab1, A2, ab2, out);
}